// round 1
// baseline (speedup 1.0000x reference)
#include <cuda_runtime.h>

// Problem-size constants (shapes are fixed for this dataset).
#define NMAX 100000
#define EMAX 1600000
#define TOTMAX (EMAX + NMAX)

// ---------------- scratch (static device globals; no allocation) -------------
__device__ int   g_deg[NMAX];
__device__ int   g_fill[NMAX];
__device__ float g_dinv[NMAX];
__device__ int   g_rowptr[NMAX + 1];
__device__ int   g_bsum[256];
__device__ int   g_col[TOTMAX];
__device__ float g_norm[TOTMAX];
__device__ float g_bufA[(size_t)NMAX * 128];
__device__ float g_bufB[(size_t)NMAX * 128];

// ---------------- preprocessing kernels --------------------------------------

__global__ void zero_kernel(int n) {
    int i = blockIdx.x * blockDim.x + threadIdx.x;
    if (i < n) { g_deg[i] = 0; g_fill[i] = 0; }
}

__global__ void degree_kernel(const int* __restrict__ ei, int e) {
    int i = blockIdx.x * blockDim.x + threadIdx.x;
    if (i < e) atomicAdd(&g_deg[ei[e + i]], 1);   // dst = ei[E + i]
}

__global__ void dinv_kernel(int n) {
    int i = blockIdx.x * blockDim.x + threadIdx.x;
    if (i < n) g_dinv[i] = rsqrtf((float)(g_deg[i] + 1));  // +1 self-loop
}

// Block-wise inclusive scan of (deg+1) into rowptr[i+1]; block sums to g_bsum.
__global__ void scan1_kernel(int n) {
    __shared__ int s[1024];
    int t = threadIdx.x;
    int i = blockIdx.x * 1024 + t;
    int v = (i < n) ? (g_deg[i] + 1) : 0;
    s[t] = v;
    __syncthreads();
    for (int off = 1; off < 1024; off <<= 1) {
        int x = (t >= off) ? s[t - off] : 0;
        __syncthreads();
        s[t] += x;
        __syncthreads();
    }
    if (i < n) g_rowptr[i + 1] = s[t];
    if (t == 1023) g_bsum[blockIdx.x] = s[1023];
}

__global__ void scan2_kernel(int nb) {
    if (threadIdx.x == 0) {
        int run = 0;
        for (int b = 0; b < nb; b++) { int v = g_bsum[b]; g_bsum[b] = run; run += v; }
    }
}

__global__ void scan3_kernel(int n) {
    int i = blockIdx.x * blockDim.x + threadIdx.x;
    if (i < n) g_rowptr[i + 1] += g_bsum[i >> 10];
    if (i == 0) g_rowptr[0] = 0;
}

// Scatter edges (+self-loops) into CSR sorted by dst; compute norm per entry.
__global__ void fill_kernel(const int* __restrict__ ei, int e, int n) {
    int i = blockIdx.x * blockDim.x + threadIdx.x;
    if (i >= e + n) return;
    int s, d;
    if (i < e) { s = ei[i]; d = ei[e + i]; }
    else       { s = d = i - e; }
    int pos = atomicAdd(&g_fill[d], 1);
    int idx = g_rowptr[d] + pos;
    g_col[idx] = s;
    g_norm[idx] = g_dinv[s] * g_dinv[d];
}

// ---------------- GEMMs ------------------------------------------------------

// C[n,128] = A[n,128] @ W[128,128].  BM=64, BN=128, BK=16, 256 threads, 4x8 tile.
__global__ void gemm128_kernel(const float* __restrict__ A, const float* __restrict__ W,
                               float* __restrict__ C, int n) {
    __shared__ float As[16][64];
    __shared__ float Ws[16][128];
    const int tid = threadIdx.x;
    const int tr = tid >> 4;        // 0..15 -> rows tr*4..tr*4+3
    const int tc = tid & 15;        // 0..15 -> cols tc*8..tc*8+7
    const int row0 = blockIdx.x * 64;
    const int ar = tid >> 2;        // 0..63 (A-load row)
    const int akb = (tid & 3) * 4;  // A-load col base

    float acc[4][8];
#pragma unroll
    for (int i = 0; i < 4; i++)
#pragma unroll
        for (int j = 0; j < 8; j++) acc[i][j] = 0.f;

    for (int k0 = 0; k0 < 128; k0 += 16) {
        float4 av = make_float4(0.f, 0.f, 0.f, 0.f);
        if (row0 + ar < n)
            av = *(const float4*)(A + (size_t)(row0 + ar) * 128 + k0 + akb);
        As[akb + 0][ar] = av.x;
        As[akb + 1][ar] = av.y;
        As[akb + 2][ar] = av.z;
        As[akb + 3][ar] = av.w;
#pragma unroll
        for (int l = 0; l < 2; l++) {
            int f = tid + l * 256;
            int k = f >> 5, c = (f & 31) * 4;
            *(float4*)&Ws[k][c] = *(const float4*)(W + (size_t)(k0 + k) * 128 + c);
        }
        __syncthreads();
#pragma unroll
        for (int kk = 0; kk < 16; kk++) {
            float4 a  = *(const float4*)&As[kk][tr * 4];
            float4 w0 = *(const float4*)&Ws[kk][tc * 8];
            float4 w1 = *(const float4*)&Ws[kk][tc * 8 + 4];
            float aa[4] = {a.x, a.y, a.z, a.w};
            float ww[8] = {w0.x, w0.y, w0.z, w0.w, w1.x, w1.y, w1.z, w1.w};
#pragma unroll
            for (int i = 0; i < 4; i++)
#pragma unroll
                for (int j = 0; j < 8; j++) acc[i][j] = fmaf(aa[i], ww[j], acc[i][j]);
        }
        __syncthreads();
    }
#pragma unroll
    for (int i = 0; i < 4; i++) {
        int r = row0 + tr * 4 + i;
        if (r < n) {
            float4 o0 = make_float4(acc[i][0], acc[i][1], acc[i][2], acc[i][3]);
            float4 o1 = make_float4(acc[i][4], acc[i][5], acc[i][6], acc[i][7]);
            *(float4*)(C + (size_t)r * 128 + tc * 8)     = o0;
            *(float4*)(C + (size_t)r * 128 + tc * 8 + 4) = o1;
        }
    }
}

// C[n,40] = A[n,128] @ W[128,40].  BM=64, BN=40, BK=16, 128 threads, 4x5 tile.
__global__ void gemm40_kernel(const float* __restrict__ A, const float* __restrict__ W,
                              float* __restrict__ C, int n) {
    __shared__ float As[16][64];
    __shared__ float Ws[16][40];
    const int tid = threadIdx.x;       // 0..127
    const int tr = tid >> 3;           // 0..15 -> rows tr*4..
    const int tc = tid & 7;            // 0..7  -> cols tc*5..
    const int row0 = blockIdx.x * 64;
    const int ar = tid >> 1;           // 0..63
    const int akb = (tid & 1) * 8;     // col base (8 floats per thread)

    float acc[4][5];
#pragma unroll
    for (int i = 0; i < 4; i++)
#pragma unroll
        for (int j = 0; j < 5; j++) acc[i][j] = 0.f;

    for (int k0 = 0; k0 < 128; k0 += 16) {
        float4 a0 = make_float4(0.f, 0.f, 0.f, 0.f);
        float4 a1 = make_float4(0.f, 0.f, 0.f, 0.f);
        if (row0 + ar < n) {
            const float* p = A + (size_t)(row0 + ar) * 128 + k0 + akb;
            a0 = *(const float4*)p;
            a1 = *(const float4*)(p + 4);
        }
        As[akb + 0][ar] = a0.x; As[akb + 1][ar] = a0.y;
        As[akb + 2][ar] = a0.z; As[akb + 3][ar] = a0.w;
        As[akb + 4][ar] = a1.x; As[akb + 5][ar] = a1.y;
        As[akb + 6][ar] = a1.z; As[akb + 7][ar] = a1.w;
        for (int i = tid; i < 16 * 40; i += 128) {
            int k = i / 40, c = i % 40;
            Ws[k][c] = W[(size_t)(k0 + k) * 40 + c];
        }
        __syncthreads();
#pragma unroll
        for (int kk = 0; kk < 16; kk++) {
            float4 a = *(const float4*)&As[kk][tr * 4];
            float aa[4] = {a.x, a.y, a.z, a.w};
            float ww[5];
#pragma unroll
            for (int j = 0; j < 5; j++) ww[j] = Ws[kk][tc * 5 + j];
#pragma unroll
            for (int i = 0; i < 4; i++)
#pragma unroll
                for (int j = 0; j < 5; j++) acc[i][j] = fmaf(aa[i], ww[j], acc[i][j]);
        }
        __syncthreads();
    }
#pragma unroll
    for (int i = 0; i < 4; i++) {
        int r = row0 + tr * 4 + i;
        if (r < n) {
#pragma unroll
            for (int j = 0; j < 5; j++) C[(size_t)r * 40 + tc * 5 + j] = acc[i][j];
        }
    }
}

// ---------------- aggregation (one warp per destination node) ----------------

template <int F, bool RELU>
__global__ void aggregate_kernel(const float* __restrict__ tmp, const float* __restrict__ bias,
                                 float* __restrict__ out, int n) {
    int w = (blockIdx.x * blockDim.x + threadIdx.x) >> 5;
    int lane = threadIdx.x & 31;
    if (w >= n) return;
    int beg = g_rowptr[w], end = g_rowptr[w + 1];

    if (F == 128) {
        float4 acc = make_float4(0.f, 0.f, 0.f, 0.f);
        for (int e = beg; e < end; e++) {
            int s = g_col[e];
            float nw = g_norm[e];
            float4 v = *(const float4*)(tmp + (size_t)s * 128 + lane * 4);
            acc.x = fmaf(nw, v.x, acc.x);
            acc.y = fmaf(nw, v.y, acc.y);
            acc.z = fmaf(nw, v.z, acc.z);
            acc.w = fmaf(nw, v.w, acc.w);
        }
        float4 b = *(const float4*)(bias + lane * 4);
        acc.x += b.x; acc.y += b.y; acc.z += b.z; acc.w += b.w;
        if (RELU) {
            acc.x = fmaxf(acc.x, 0.f); acc.y = fmaxf(acc.y, 0.f);
            acc.z = fmaxf(acc.z, 0.f); acc.w = fmaxf(acc.w, 0.f);
        }
        *(float4*)(out + (size_t)w * 128 + lane * 4) = acc;
    } else {  // F == 40
        float a0 = 0.f, a1 = 0.f;
        for (int e = beg; e < end; e++) {
            int s = g_col[e];
            float nw = g_norm[e];
            const float* row = tmp + (size_t)s * 40;
            a0 = fmaf(nw, row[lane], a0);
            if (lane < 8) a1 = fmaf(nw, row[32 + lane], a1);
        }
        a0 += bias[lane];
        if (lane < 8) a1 += bias[32 + lane];
        if (RELU) {
            a0 = fmaxf(a0, 0.f);
            if (lane < 8) a1 = fmaxf(a1, 0.f);
        }
        out[(size_t)w * 40 + lane] = a0;
        if (lane < 8) out[(size_t)w * 40 + 32 + lane] = a1;
    }
}

// ---------------- launch -----------------------------------------------------

extern "C" void kernel_launch(void* const* d_in, const int* in_sizes, int n_in,
                              void* d_out, int out_size) {
    const float* x  = (const float*)d_in[0];
    const int*   ei = (const int*)d_in[1];
    const float* W0 = (const float*)d_in[2];
    const float* b0 = (const float*)d_in[3];
    const float* W1 = (const float*)d_in[4];
    const float* b1 = (const float*)d_in[5];
    const float* W2 = (const float*)d_in[6];
    const float* b2 = (const float*)d_in[7];
    float* out = (float*)d_out;

    const int n = in_sizes[0] / 128;
    const int e = in_sizes[1] / 2;

    float *bufA = nullptr, *bufB = nullptr;
    cudaGetSymbolAddress((void**)&bufA, g_bufA);
    cudaGetSymbolAddress((void**)&bufB, g_bufB);

    const int nb = (n + 1023) / 1024;

    zero_kernel<<<(n + 255) / 256, 256>>>(n);
    degree_kernel<<<(e + 255) / 256, 256>>>(ei, e);
    dinv_kernel<<<(n + 255) / 256, 256>>>(n);
    scan1_kernel<<<nb, 1024>>>(n);
    scan2_kernel<<<1, 32>>>(nb);
    scan3_kernel<<<(n + 255) / 256, 256>>>(n);
    fill_kernel<<<(e + n + 255) / 256, 256>>>(ei, e, n);

    const int gb = (n + 63) / 64;
    const int ab128 = (n + 7) / 8;   // 8 warps / block

    // layer 0: x @ W0 -> bufA ; aggregate+bias+relu -> bufB
    gemm128_kernel<<<gb, 256>>>(x, W0, bufA, n);
    aggregate_kernel<128, true><<<ab128, 256>>>(bufA, b0, bufB, n);

    // layer 1
    gemm128_kernel<<<gb, 256>>>(bufB, W1, bufA, n);
    aggregate_kernel<128, true><<<ab128, 256>>>(bufA, b1, bufB, n);

    // layer 2: project to 40, aggregate, +bias (no relu) -> out
    gemm40_kernel<<<gb, 128>>>(bufB, W2, bufA, n);
    aggregate_kernel<40, false><<<ab128, 256>>>(bufA, b2, out, n);
}

// round 2
// speedup vs baseline: 1.3447x; 1.3447x over previous
#include <cuda_runtime.h>
#include <cuda_fp16.h>

#define NMAX 100000
#define EMAX 1600000
#define TOTMAX (EMAX + NMAX)

// ---------------- scratch (static device globals; no allocation) -------------
__device__ int    g_deg[NMAX];
__device__ float  g_dinv[NMAX];
__device__ int    g_rowptr[NMAX + 1];
__device__ int    g_bsum[128];
__device__ int    g_col[TOTMAX];
__device__ float  g_norm[TOTMAX];
__device__ __half g_bufH[(size_t)NMAX * 128];   // fp16 gather buffer (GEMM out)
__device__ float  g_bufF[(size_t)NMAX * 128];   // fp32 aggregate out / GEMM in

// ---------------- preprocessing ----------------------------------------------

__global__ void zero_kernel(int n) {
    int i = blockIdx.x * blockDim.x + threadIdx.x;
    if (i < n) g_deg[i] = 0;
}

__global__ void degree_kernel(const int* __restrict__ ei, int e) {
    int i = blockIdx.x * blockDim.x + threadIdx.x;
    if (i < e) atomicAdd(&g_deg[ei[e + i]], 1);   // dst = ei[E + i]
}

// Block-wise inclusive scan of (deg+1); also computes dinv. Block sums -> g_bsum.
__global__ void scan1_kernel(int n) {
    __shared__ int s[1024];
    int t = threadIdx.x;
    int i = blockIdx.x * 1024 + t;
    int v = 0;
    if (i < n) {
        v = g_deg[i] + 1;                  // +1 self-loop
        g_dinv[i] = rsqrtf((float)v);
    }
    s[t] = v;
    __syncthreads();
    for (int off = 1; off < 1024; off <<= 1) {
        int x = (t >= off) ? s[t - off] : 0;
        __syncthreads();
        s[t] += x;
        __syncthreads();
    }
    if (i < n) g_rowptr[i + 1] = s[t];
    if (t == 1023) g_bsum[blockIdx.x] = s[1023];
}

// Parallel exclusive scan of up to 128 block sums (one block).
__global__ void scan2_kernel(int nb) {
    __shared__ int ws[4];
    int t = threadIdx.x;              // 128 threads
    int lane = t & 31, w = t >> 5;
    int orig = (t < nb) ? g_bsum[t] : 0;
    int v = orig;
    for (int off = 1; off < 32; off <<= 1) {
        int x = __shfl_up_sync(0xffffffffu, v, off);
        if (lane >= off) v += x;
    }
    if (lane == 31) ws[w] = v;
    __syncthreads();
    int add = 0;
    for (int i = 0; i < w; i++) add += ws[i];
    v += add;
    if (t < nb) g_bsum[t] = v - orig;  // exclusive
}

__global__ void scan3_kernel(int n) {
    int i = blockIdx.x * blockDim.x + threadIdx.x;
    if (i < n) g_rowptr[i + 1] += g_bsum[i >> 10];
    if (i == 0) g_rowptr[0] = 0;
}

// Scatter edges into CSR sorted by dst. Edge slots via atomicSub on g_deg
// (consumes the counts); self-loop gets the fixed last slot rowptr[d+1]-1.
__global__ void fill_kernel(const int* __restrict__ ei, int e, int n) {
    int i = blockIdx.x * blockDim.x + threadIdx.x;
    if (i < e) {
        int s = ei[i], d = ei[e + i];
        int pos = atomicSub(&g_deg[d], 1) - 1;
        int idx = g_rowptr[d] + pos;
        g_col[idx] = s;
        g_norm[idx] = g_dinv[s] * g_dinv[d];
    } else if (i < e + n) {
        int d = i - e;
        int idx = g_rowptr[d + 1] - 1;
        g_col[idx] = d;
        float dv = g_dinv[d];
        g_norm[idx] = dv * dv;
    }
}

// ---------------- GEMMs ------------------------------------------------------

// C[n,128](half) = A[n,128](f32) @ W[128,128](f32). BM=BN=128, BK=16,
// 256 threads, 8x8 register tile.
__global__ void gemm128_kernel(const float* __restrict__ A, const float* __restrict__ W,
                               __half2* __restrict__ C, int n) {
    __shared__ float As[16][132];   // transposed, padded
    __shared__ float Ws[16][128];
    const int tid = threadIdx.x;
    const int tr = tid >> 4;        // 0..15 -> rows tr*8..
    const int tc = tid & 15;        // 0..15 -> cols tc*8..
    const int row0 = blockIdx.x * 128;

    float acc[8][8];
#pragma unroll
    for (int i = 0; i < 8; i++)
#pragma unroll
        for (int j = 0; j < 8; j++) acc[i][j] = 0.f;

    for (int k0 = 0; k0 < 128; k0 += 16) {
#pragma unroll
        for (int l = 0; l < 2; l++) {
            int f = tid + l * 256;          // 0..511
            int r = f >> 2, c4 = f & 3;
            float4 av = make_float4(0.f, 0.f, 0.f, 0.f);
            if (row0 + r < n)
                av = *(const float4*)(A + (size_t)(row0 + r) * 128 + k0 + c4 * 4);
            As[c4 * 4 + 0][r] = av.x;
            As[c4 * 4 + 1][r] = av.y;
            As[c4 * 4 + 2][r] = av.z;
            As[c4 * 4 + 3][r] = av.w;
            int k = f >> 5, c = (f & 31) * 4;
            *(float4*)&Ws[k][c] = *(const float4*)(W + (size_t)(k0 + k) * 128 + c);
        }
        __syncthreads();
#pragma unroll
        for (int kk = 0; kk < 16; kk++) {
            float4 a0 = *(const float4*)&As[kk][tr * 8];
            float4 a1 = *(const float4*)&As[kk][tr * 8 + 4];
            float4 w0 = *(const float4*)&Ws[kk][tc * 8];
            float4 w1 = *(const float4*)&Ws[kk][tc * 8 + 4];
            float aa[8] = {a0.x, a0.y, a0.z, a0.w, a1.x, a1.y, a1.z, a1.w};
            float ww[8] = {w0.x, w0.y, w0.z, w0.w, w1.x, w1.y, w1.z, w1.w};
#pragma unroll
            for (int i = 0; i < 8; i++)
#pragma unroll
                for (int j = 0; j < 8; j++) acc[i][j] = fmaf(aa[i], ww[j], acc[i][j]);
        }
        __syncthreads();
    }
#pragma unroll
    for (int i = 0; i < 8; i++) {
        int r = row0 + tr * 8 + i;
        if (r < n) {
#pragma unroll
            for (int j = 0; j < 4; j++)
                C[(size_t)r * 64 + tc * 4 + j] =
                    __floats2half2_rn(acc[i][2 * j], acc[i][2 * j + 1]);
        }
    }
}

// C[n,40](half) = A[n,128](f32) @ W[128,40](f32). BM=64, 128 threads, 4x5 tile.
__global__ void gemm40_kernel(const float* __restrict__ A, const float* __restrict__ W,
                              __half* __restrict__ C, int n) {
    __shared__ float As[16][64];
    __shared__ float Ws[16][40];
    const int tid = threadIdx.x;       // 0..127
    const int tr = tid >> 3;           // 0..15
    const int tc = tid & 7;            // 0..7
    const int row0 = blockIdx.x * 64;
    const int ar = tid >> 1;           // 0..63
    const int akb = (tid & 1) * 8;

    float acc[4][5];
#pragma unroll
    for (int i = 0; i < 4; i++)
#pragma unroll
        for (int j = 0; j < 5; j++) acc[i][j] = 0.f;

    for (int k0 = 0; k0 < 128; k0 += 16) {
        float4 a0 = make_float4(0.f, 0.f, 0.f, 0.f);
        float4 a1 = make_float4(0.f, 0.f, 0.f, 0.f);
        if (row0 + ar < n) {
            const float* p = A + (size_t)(row0 + ar) * 128 + k0 + akb;
            a0 = *(const float4*)p;
            a1 = *(const float4*)(p + 4);
        }
        As[akb + 0][ar] = a0.x; As[akb + 1][ar] = a0.y;
        As[akb + 2][ar] = a0.z; As[akb + 3][ar] = a0.w;
        As[akb + 4][ar] = a1.x; As[akb + 5][ar] = a1.y;
        As[akb + 6][ar] = a1.z; As[akb + 7][ar] = a1.w;
        for (int i = tid; i < 16 * 40; i += 128) {
            int k = i / 40, c = i % 40;
            Ws[k][c] = W[(size_t)(k0 + k) * 40 + c];
        }
        __syncthreads();
#pragma unroll
        for (int kk = 0; kk < 16; kk++) {
            float4 a = *(const float4*)&As[kk][tr * 4];
            float aa[4] = {a.x, a.y, a.z, a.w};
            float ww[5];
#pragma unroll
            for (int j = 0; j < 5; j++) ww[j] = Ws[kk][tc * 5 + j];
#pragma unroll
            for (int i = 0; i < 4; i++)
#pragma unroll
                for (int j = 0; j < 5; j++) acc[i][j] = fmaf(aa[i], ww[j], acc[i][j]);
        }
        __syncthreads();
    }
#pragma unroll
    for (int i = 0; i < 4; i++) {
        int r = row0 + tr * 4 + i;
        if (r < n) {
#pragma unroll
            for (int j = 0; j < 5; j++)
                C[(size_t)r * 40 + tc * 5 + j] = __float2half(acc[i][j]);
        }
    }
}

// ---------------- aggregation (one warp per destination node) ----------------

template <bool RELU>
__global__ void aggregate128_kernel(const __half2* __restrict__ tmp,
                                    const float* __restrict__ bias,
                                    float2* __restrict__ out, int n) {
    int w = (blockIdx.x * blockDim.x + threadIdx.x) >> 5;
    int lane = threadIdx.x & 31;
    if (w >= n) return;
    int beg = g_rowptr[w], end = g_rowptr[w + 1];

    float2 acc0 = make_float2(0.f, 0.f);
    float2 acc1 = make_float2(0.f, 0.f);
    for (int e = beg; e < end; e++) {
        int s = g_col[e];
        float nw = g_norm[e];
        float2 f0 = __half22float2(tmp[(size_t)s * 64 + lane]);
        float2 f1 = __half22float2(tmp[(size_t)s * 64 + 32 + lane]);
        acc0.x = fmaf(nw, f0.x, acc0.x);
        acc0.y = fmaf(nw, f0.y, acc0.y);
        acc1.x = fmaf(nw, f1.x, acc1.x);
        acc1.y = fmaf(nw, f1.y, acc1.y);
    }
    acc0.x += bias[2 * lane];
    acc0.y += bias[2 * lane + 1];
    acc1.x += bias[64 + 2 * lane];
    acc1.y += bias[64 + 2 * lane + 1];
    if (RELU) {
        acc0.x = fmaxf(acc0.x, 0.f); acc0.y = fmaxf(acc0.y, 0.f);
        acc1.x = fmaxf(acc1.x, 0.f); acc1.y = fmaxf(acc1.y, 0.f);
    }
    out[(size_t)w * 64 + lane] = acc0;
    out[(size_t)w * 64 + 32 + lane] = acc1;
}

__global__ void aggregate40_kernel(const __half* __restrict__ tmp,
                                   const float* __restrict__ bias,
                                   float* __restrict__ out, int n) {
    int w = (blockIdx.x * blockDim.x + threadIdx.x) >> 5;
    int lane = threadIdx.x & 31;
    if (w >= n) return;
    int beg = g_rowptr[w], end = g_rowptr[w + 1];

    float a0 = 0.f, a1 = 0.f;
    for (int e = beg; e < end; e++) {
        int s = g_col[e];
        float nw = g_norm[e];
        const __half* row = tmp + (size_t)s * 40;
        a0 = fmaf(nw, __half2float(row[lane]), a0);
        if (lane < 8) a1 = fmaf(nw, __half2float(row[32 + lane]), a1);
    }
    a0 += bias[lane];
    if (lane < 8) a1 += bias[32 + lane];
    out[(size_t)w * 40 + lane] = a0;
    if (lane < 8) out[(size_t)w * 40 + 32 + lane] = a1;
}

// ---------------- launch -----------------------------------------------------

extern "C" void kernel_launch(void* const* d_in, const int* in_sizes, int n_in,
                              void* d_out, int out_size) {
    const float* x  = (const float*)d_in[0];
    const int*   ei = (const int*)d_in[1];
    const float* W0 = (const float*)d_in[2];
    const float* b0 = (const float*)d_in[3];
    const float* W1 = (const float*)d_in[4];
    const float* b1 = (const float*)d_in[5];
    const float* W2 = (const float*)d_in[6];
    const float* b2 = (const float*)d_in[7];
    float* out = (float*)d_out;

    const int n = in_sizes[0] / 128;
    const int e = in_sizes[1] / 2;

    __half* bufH = nullptr;
    float*  bufF = nullptr;
    cudaGetSymbolAddress((void**)&bufH, g_bufH);
    cudaGetSymbolAddress((void**)&bufF, g_bufF);

    static cudaStream_t s_side = nullptr;
    static cudaEvent_t ev_fork = nullptr, ev_join = nullptr;
    if (!s_side) {
        cudaStreamCreateWithFlags(&s_side, cudaStreamNonBlocking);
        cudaEventCreateWithFlags(&ev_fork, cudaEventDisableTiming);
        cudaEventCreateWithFlags(&ev_join, cudaEventDisableTiming);
    }

    const int nb = (n + 1023) / 1024;
    const int gb = (n + 127) / 128;       // gemm128 blocks
    const int gb40 = (n + 63) / 64;       // gemm40 blocks
    const int ab = (n + 7) / 8;           // aggregate blocks (8 warps)

    // Fork: layer-0 GEMM (independent of graph preprocessing) on side stream.
    cudaEventRecord(ev_fork, 0);
    cudaStreamWaitEvent(s_side, ev_fork, 0);
    gemm128_kernel<<<gb, 256, 0, s_side>>>(x, W0, (__half2*)bufH, n);
    cudaEventRecord(ev_join, s_side);

    // Preprocessing chain on main stream (overlapped with gemm0).
    zero_kernel<<<(n + 255) / 256, 256>>>(n);
    degree_kernel<<<(e + 255) / 256, 256>>>(ei, e);
    scan1_kernel<<<nb, 1024>>>(n);
    scan2_kernel<<<1, 128>>>(nb);
    scan3_kernel<<<(n + 255) / 256, 256>>>(n);
    fill_kernel<<<(e + n + 255) / 256, 256>>>(ei, e, n);

    // Join, then alternate aggregate/GEMM.
    cudaStreamWaitEvent(0, ev_join, 0);
    aggregate128_kernel<true><<<ab, 256>>>((const __half2*)bufH, b0, (float2*)bufF, n);
    gemm128_kernel<<<gb, 256>>>(bufF, W1, (__half2*)bufH, n);
    aggregate128_kernel<true><<<ab, 256>>>((const __half2*)bufH, b1, (float2*)bufF, n);
    gemm40_kernel<<<gb40, 128>>>(bufF, W2, bufH, n);
    aggregate40_kernel<<<ab, 256>>>(bufH, b2, out, n);
}

// round 5
// speedup vs baseline: 1.6326x; 1.2140x over previous
#include <cuda_runtime.h>
#include <cuda_fp16.h>
#include <mma.h>

using namespace nvcuda;

#define NMAX 100000
#define EMAX 1600000
#define TOTMAX (EMAX + NMAX)
#define PAD_ROWS 64   // row padding so wmma fragment loads past n are in-bounds

// ---------------- scratch (static device globals; no allocation) -------------
__device__ int    g_deg[NMAX];
__device__ float  g_dinv[NMAX];
__device__ int    g_rowptr[NMAX + 1];
__device__ int    g_bsum[128];
__device__ int    g_col[TOTMAX];
__device__ float  g_norm[TOTMAX];
__device__ __half g_xh[(size_t)(NMAX + PAD_ROWS) * 128];
__device__ __half g_bufA[(size_t)(NMAX + PAD_ROWS) * 128];
__device__ __half g_bufB[(size_t)(NMAX + PAD_ROWS) * 128];
__device__ __half g_w0h[128 * 128];
__device__ __half g_w1h[128 * 128];
__device__ __half g_w2h[128 * 48];   // W2 padded 40 -> 48 cols (zeros)

// ---------------- preprocessing ----------------------------------------------

__global__ void zero_kernel(int n) {
    int i = blockIdx.x * blockDim.x + threadIdx.x;
    if (i < n) g_deg[i] = 0;
}

__global__ void degree_kernel(const int* __restrict__ ei, int e) {
    int i = blockIdx.x * blockDim.x + threadIdx.x;
    if (i < e) atomicAdd(&g_deg[ei[e + i]], 1);   // dst = ei[E + i]
}

__global__ void scan1_kernel(int n) {
    __shared__ int s[1024];
    int t = threadIdx.x;
    int i = blockIdx.x * 1024 + t;
    int v = 0;
    if (i < n) {
        v = g_deg[i] + 1;                  // +1 self-loop
        g_dinv[i] = rsqrtf((float)v);
    }
    s[t] = v;
    __syncthreads();
    for (int off = 1; off < 1024; off <<= 1) {
        int x = (t >= off) ? s[t - off] : 0;
        __syncthreads();
        s[t] += x;
        __syncthreads();
    }
    if (i < n) g_rowptr[i + 1] = s[t];
    if (t == 1023) g_bsum[blockIdx.x] = s[1023];
}

__global__ void scan2_kernel(int nb) {
    __shared__ int ws[4];
    int t = threadIdx.x;              // 128 threads
    int lane = t & 31, w = t >> 5;
    int orig = (t < nb) ? g_bsum[t] : 0;
    int v = orig;
    for (int off = 1; off < 32; off <<= 1) {
        int x = __shfl_up_sync(0xffffffffu, v, off);
        if (lane >= off) v += x;
    }
    if (lane == 31) ws[w] = v;
    __syncthreads();
    int add = 0;
    for (int i = 0; i < w; i++) add += ws[i];
    v += add;
    if (t < nb) g_bsum[t] = v - orig;  // exclusive
}

__global__ void scan3_kernel(int n) {
    int i = blockIdx.x * blockDim.x + threadIdx.x;
    if (i < n) g_rowptr[i + 1] += g_bsum[i >> 10];
    if (i == 0) g_rowptr[0] = 0;
}

__global__ void fill_kernel(const int* __restrict__ ei, int e, int n) {
    int i = blockIdx.x * blockDim.x + threadIdx.x;
    if (i < e) {
        int s = ei[i], d = ei[e + i];
        int pos = atomicSub(&g_deg[d], 1) - 1;
        int idx = g_rowptr[d] + pos;
        g_col[idx] = s;
        g_norm[idx] = g_dinv[s] * g_dinv[d];
    } else if (i < e + n) {
        int d = i - e;
        int idx = g_rowptr[d + 1] - 1;
        g_col[idx] = d;
        float dv = g_dinv[d];
        g_norm[idx] = dv * dv;
    }
}

// ---------------- fp32 -> fp16 converters -------------------------------------

__global__ void convert_x_kernel(const float4* __restrict__ x, __half2* __restrict__ xh,
                                 int n8) {
    int i = blockIdx.x * blockDim.x + threadIdx.x;   // one per 8 floats
    if (i >= n8) return;
    float4 a = x[2 * i], b = x[2 * i + 1];
    xh[4 * i + 0] = __floats2half2_rn(a.x, a.y);
    xh[4 * i + 1] = __floats2half2_rn(a.z, a.w);
    xh[4 * i + 2] = __floats2half2_rn(b.x, b.y);
    xh[4 * i + 3] = __floats2half2_rn(b.z, b.w);
}

__global__ void convert_w_kernel(const float* __restrict__ W0, const float* __restrict__ W1,
                                 const float* __restrict__ W2) {
    int i = blockIdx.x * blockDim.x + threadIdx.x;   // 0 .. 38911
    if (i < 16384) {
        g_w0h[i] = __float2half(W0[i]);
    } else if (i < 32768) {
        g_w1h[i - 16384] = __float2half(W1[i - 16384]);
    } else if (i < 32768 + 128 * 48) {
        int j = i - 32768;
        int r = j / 48, c = j % 48;
        g_w2h[j] = (c < 40) ? __float2half(W2[r * 40 + c]) : __half(0.f);
    }
}

// ---------------- tensor-core GEMMs -------------------------------------------

// C[n,128](half) = A[n,128](half) @ W[128,128](half), fp32 accum.
// 256 threads = 8 warps in 2(m) x 4(n); each warp computes 32x32.
__global__ __launch_bounds__(256) void gemm128_wmma(const __half* __restrict__ A,
                                                    const __half* __restrict__ W,
                                                    __half2* __restrict__ C, int n) {
    __shared__ float cs[8][32 * 36];
    const int w = threadIdx.x >> 5;
    const int lane = threadIdx.x & 31;
    const int wm = w >> 2, wn = w & 3;
    const int row0 = blockIdx.x * 64 + wm * 32;

    wmma::fragment<wmma::accumulator, 16, 16, 16, float> acc[2][2];
#pragma unroll
    for (int i = 0; i < 2; i++)
#pragma unroll
        for (int j = 0; j < 2; j++) wmma::fill_fragment(acc[i][j], 0.f);

#pragma unroll
    for (int k = 0; k < 8; k++) {
        wmma::fragment<wmma::matrix_a, 16, 16, 16, __half, wmma::row_major> a0, a1;
        wmma::fragment<wmma::matrix_b, 16, 16, 16, __half, wmma::row_major> b0, b1;
        wmma::load_matrix_sync(a0, A + (size_t)row0 * 128 + k * 16, 128);
        wmma::load_matrix_sync(a1, A + (size_t)(row0 + 16) * 128 + k * 16, 128);
        wmma::load_matrix_sync(b0, W + (size_t)k * 16 * 128 + wn * 32, 128);
        wmma::load_matrix_sync(b1, W + (size_t)k * 16 * 128 + wn * 32 + 16, 128);
        wmma::mma_sync(acc[0][0], a0, b0, acc[0][0]);
        wmma::mma_sync(acc[0][1], a0, b1, acc[0][1]);
        wmma::mma_sync(acc[1][0], a1, b0, acc[1][0]);
        wmma::mma_sync(acc[1][1], a1, b1, acc[1][1]);
    }

#pragma unroll
    for (int i = 0; i < 2; i++)
#pragma unroll
        for (int j = 0; j < 2; j++)
            wmma::store_matrix_sync(&cs[w][(i * 16) * 36 + j * 16], acc[i][j], 36,
                                    wmma::mem_row_major);
    __syncwarp();

    // 32 rows x 32 cols per warp -> half2 stores, 2 rows x 16 half2 per iter.
    const int rsub = lane >> 4;          // 0..1
    const int csub = lane & 15;          // 0..15
#pragma unroll
    for (int it = 0; it < 16; it++) {
        int r = it * 2 + rsub;
        int gr = row0 + r;
        if (gr < n) {
            float v0 = cs[w][r * 36 + csub * 2];
            float v1 = cs[w][r * 36 + csub * 2 + 1];
            C[(size_t)gr * 64 + wn * 16 + csub] = __floats2half2_rn(v0, v1);
        }
    }
}

// C[n,48](half) = A[n,128](half) @ W2h[128,48](half). 8 warps, 16 rows each.
__global__ __launch_bounds__(256) void gemm40_wmma(const __half* __restrict__ A,
                                                   __half2* __restrict__ C, int n) {
    __shared__ float cs[8][16 * 48];
    const int w = threadIdx.x >> 5;
    const int lane = threadIdx.x & 31;
    const int row0 = blockIdx.x * 128 + w * 16;

    wmma::fragment<wmma::accumulator, 16, 16, 16, float> acc[3];
#pragma unroll
    for (int j = 0; j < 3; j++) wmma::fill_fragment(acc[j], 0.f);

#pragma unroll
    for (int k = 0; k < 8; k++) {
        wmma::fragment<wmma::matrix_a, 16, 16, 16, __half, wmma::row_major> a;
        wmma::load_matrix_sync(a, A + (size_t)row0 * 128 + k * 16, 128);
#pragma unroll
        for (int j = 0; j < 3; j++) {
            wmma::fragment<wmma::matrix_b, 16, 16, 16, __half, wmma::row_major> b;
            wmma::load_matrix_sync(b, g_w2h + (size_t)k * 16 * 48 + j * 16, 48);
            wmma::mma_sync(acc[j], a, b, acc[j]);
        }
    }
#pragma unroll
    for (int j = 0; j < 3; j++)
        wmma::store_matrix_sync(&cs[w][j * 16], acc[j], 48, wmma::mem_row_major);
    __syncwarp();

    for (int i = lane; i < 16 * 24; i += 32) {
        int r = i / 24, c = i % 24;
        int gr = row0 + r;
        if (gr < n)
            C[(size_t)gr * 24 + c] = __floats2half2_rn(cs[w][r * 48 + 2 * c],
                                                       cs[w][r * 48 + 2 * c + 1]);
    }
}

// ---------------- aggregation (one warp per destination node) ----------------

__global__ void aggregate128_kernel(const __half2* __restrict__ tmp,
                                    const float* __restrict__ bias,
                                    __half2* __restrict__ out, int n) {
    int w = (blockIdx.x * blockDim.x + threadIdx.x) >> 5;
    int lane = threadIdx.x & 31;
    if (w >= n) return;
    int beg = g_rowptr[w], end = g_rowptr[w + 1];

    float2 acc0 = make_float2(0.f, 0.f);
    float2 acc1 = make_float2(0.f, 0.f);
    for (int e = beg; e < end; e++) {
        int s = g_col[e];
        float nw = g_norm[e];
        float2 f0 = __half22float2(tmp[(size_t)s * 64 + lane]);
        float2 f1 = __half22float2(tmp[(size_t)s * 64 + 32 + lane]);
        acc0.x = fmaf(nw, f0.x, acc0.x);
        acc0.y = fmaf(nw, f0.y, acc0.y);
        acc1.x = fmaf(nw, f1.x, acc1.x);
        acc1.y = fmaf(nw, f1.y, acc1.y);
    }
    acc0.x += bias[2 * lane];
    acc0.y += bias[2 * lane + 1];
    acc1.x += bias[64 + 2 * lane];
    acc1.y += bias[64 + 2 * lane + 1];
    acc0.x = fmaxf(acc0.x, 0.f); acc0.y = fmaxf(acc0.y, 0.f);
    acc1.x = fmaxf(acc1.x, 0.f); acc1.y = fmaxf(acc1.y, 0.f);
    out[(size_t)w * 64 + lane] = __floats2half2_rn(acc0.x, acc0.y);
    out[(size_t)w * 64 + 32 + lane] = __floats2half2_rn(acc1.x, acc1.y);
}

// Reads padded [n,48] half rows, writes [n,40] fp32, + bias (no relu).
__global__ void aggregate40_kernel(const __half2* __restrict__ tmp,
                                   const float* __restrict__ bias,
                                   float* __restrict__ out, int n) {
    int w = (blockIdx.x * blockDim.x + threadIdx.x) >> 5;
    int lane = threadIdx.x & 31;
    if (w >= n) return;
    int beg = g_rowptr[w], end = g_rowptr[w + 1];

    float2 acc = make_float2(0.f, 0.f);
    if (lane < 24) {
        for (int e = beg; e < end; e++) {
            int s = g_col[e];
            float nw = g_norm[e];
            float2 f = __half22float2(tmp[(size_t)s * 24 + lane]);
            acc.x = fmaf(nw, f.x, acc.x);
            acc.y = fmaf(nw, f.y, acc.y);
        }
    }
    if (lane < 20) {
        out[(size_t)w * 40 + 2 * lane]     = acc.x + bias[2 * lane];
        out[(size_t)w * 40 + 2 * lane + 1] = acc.y + bias[2 * lane + 1];
    }
}

// ---------------- launch -----------------------------------------------------

extern "C" void kernel_launch(void* const* d_in, const int* in_sizes, int n_in,
                              void* d_out, int out_size) {
    const float* x  = (const float*)d_in[0];
    const int*   ei = (const int*)d_in[1];
    const float* W0 = (const float*)d_in[2];
    const float* b0 = (const float*)d_in[3];
    const float* W1 = (const float*)d_in[4];
    const float* b1 = (const float*)d_in[5];
    const float* W2 = (const float*)d_in[6];
    const float* b2 = (const float*)d_in[7];
    float* out = (float*)d_out;

    const int n = in_sizes[0] / 128;
    const int e = in_sizes[1] / 2;

    __half *xh = nullptr, *bufA = nullptr, *bufB = nullptr, *w0h = nullptr, *w1h = nullptr;
    cudaGetSymbolAddress((void**)&xh, g_xh);
    cudaGetSymbolAddress((void**)&bufA, g_bufA);
    cudaGetSymbolAddress((void**)&bufB, g_bufB);
    cudaGetSymbolAddress((void**)&w0h, g_w0h);
    cudaGetSymbolAddress((void**)&w1h, g_w1h);

    static cudaStream_t s_side = nullptr;
    static cudaEvent_t ev_fork = nullptr, ev_join = nullptr;
    if (!s_side) {
        cudaStreamCreateWithFlags(&s_side, cudaStreamNonBlocking);
        cudaEventCreateWithFlags(&ev_fork, cudaEventDisableTiming);
        cudaEventCreateWithFlags(&ev_join, cudaEventDisableTiming);
    }

    const int nb = (n + 1023) / 1024;
    const int n8 = n * 16;                    // n*128/8
    const int gb128 = (n + 63) / 64;          // gemm128 blocks (BM=64)
    const int gb40  = (n + 127) / 128;        // gemm40 blocks (BM=128)
    const int ab    = (n + 7) / 8;            // aggregate blocks (8 warps)

    // Fork: conversions + layer-0 GEMM (independent of graph preprocessing).
    cudaEventRecord(ev_fork, 0);
    cudaStreamWaitEvent(s_side, ev_fork, 0);
    convert_w_kernel<<<(32768 + 128 * 48 + 255) / 256, 256, 0, s_side>>>(W0, W1, W2);
    convert_x_kernel<<<(n8 + 255) / 256, 256, 0, s_side>>>((const float4*)x, (__half2*)xh, n8);
    gemm128_wmma<<<gb128, 256, 0, s_side>>>(xh, w0h, (__half2*)bufA, n);
    cudaEventRecord(ev_join, s_side);

    // Preprocessing chain on main stream (overlapped).
    zero_kernel<<<(n + 255) / 256, 256>>>(n);
    degree_kernel<<<(e + 255) / 256, 256>>>(ei, e);
    scan1_kernel<<<nb, 1024>>>(n);
    scan2_kernel<<<1, 128>>>(nb);
    scan3_kernel<<<(n + 255) / 256, 256>>>(n);
    fill_kernel<<<(e + n + 255) / 256, 256>>>(ei, e, n);

    cudaStreamWaitEvent(0, ev_join, 0);
    aggregate128_kernel<<<ab, 256>>>((const __half2*)bufA, b0, (__half2*)bufB, n);
    gemm128_wmma<<<gb128, 256>>>(bufB, w1h, (__half2*)bufA, n);
    aggregate128_kernel<<<ab, 256>>>((const __half2*)bufA, b1, (__half2*)bufB, n);
    gemm40_wmma<<<gb40, 256>>>(bufB, (__half2*)bufA, n);
    aggregate40_kernel<<<ab, 256>>>((const __half2*)bufA, b2, out, n);
}

// round 7
// speedup vs baseline: 2.1467x; 1.3149x over previous
#include <cuda_runtime.h>
#include <cuda_fp16.h>
#include <mma.h>

using namespace nvcuda;

#define NMAX 100000
#define EMAX 1600000
#define TOTMAX (EMAX + NMAX)
#define PAD_ROWS 128

// ---------------- scratch (static device globals; no allocation) -------------
__device__ int    g_deg[NMAX];
__device__ float  g_dinv[NMAX];
__device__ int    g_rowptr[NMAX + 1];
__device__ int    g_bsum[128];
__device__ int    g_col[TOTMAX];
__device__ float  g_norm[TOTMAX];
__device__ __half g_bufA[(size_t)(NMAX + PAD_ROWS) * 128];
__device__ __half g_bufB[(size_t)(NMAX + PAD_ROWS) * 128];
__device__ __half g_w0h[128 * 128];
__device__ __half g_w1h[128 * 128];
__device__ __half g_w2h[128 * 48];   // W2 padded 40 -> 48 cols (zeros)

// ---------------- preprocessing ----------------------------------------------

__global__ void zero_kernel(int n) {
    int i = blockIdx.x * blockDim.x + threadIdx.x;
    if (i < n) g_deg[i] = 0;
}

__global__ void degree_kernel(const int* __restrict__ ei, int e) {
    int i = blockIdx.x * blockDim.x + threadIdx.x;
    if (i < e) atomicAdd(&g_deg[ei[e + i]], 1);   // dst = ei[E + i]
}

__global__ void scan1_kernel(int n) {
    __shared__ int s[1024];
    int t = threadIdx.x;
    int i = blockIdx.x * 1024 + t;
    int v = 0;
    if (i < n) {
        v = g_deg[i] + 1;                  // +1 self-loop
        g_dinv[i] = rsqrtf((float)v);
    }
    s[t] = v;
    __syncthreads();
    for (int off = 1; off < 1024; off <<= 1) {
        int x = (t >= off) ? s[t - off] : 0;
        __syncthreads();
        s[t] += x;
        __syncthreads();
    }
    if (i < n) g_rowptr[i + 1] = s[t];
    if (t == 1023) g_bsum[blockIdx.x] = s[1023];
}

__global__ void scan2_kernel(int nb) {
    __shared__ int ws[4];
    int t = threadIdx.x;              // 128 threads
    int lane = t & 31, w = t >> 5;
    int orig = (t < nb) ? g_bsum[t] : 0;
    int v = orig;
    for (int off = 1; off < 32; off <<= 1) {
        int x = __shfl_up_sync(0xffffffffu, v, off);
        if (lane >= off) v += x;
    }
    if (lane == 31) ws[w] = v;
    __syncthreads();
    int add = 0;
    for (int i = 0; i < w; i++) add += ws[i];
    v += add;
    if (t < nb) g_bsum[t] = v - orig;  // exclusive
}

__global__ void scan3_kernel(int n) {
    int i = blockIdx.x * blockDim.x + threadIdx.x;
    if (i < n) g_rowptr[i + 1] += g_bsum[i >> 10];
    if (i == 0) g_rowptr[0] = 0;
}

__global__ void fill_kernel(const int* __restrict__ ei, int e, int n) {
    int i = blockIdx.x * blockDim.x + threadIdx.x;
    if (i < e) {
        int s = ei[i], d = ei[e + i];
        int pos = atomicSub(&g_deg[d], 1) - 1;
        int idx = g_rowptr[d] + pos;
        g_col[idx] = s;
        g_norm[idx] = g_dinv[s] * g_dinv[d];
    } else if (i < e + n) {
        int d = i - e;
        int idx = g_rowptr[d + 1] - 1;
        g_col[idx] = d;
        float dv = g_dinv[d];
        g_norm[idx] = dv * dv;
    }
}

__global__ void convert_w_kernel(const float* __restrict__ W0, const float* __restrict__ W1,
                                 const float* __restrict__ W2) {
    int i = blockIdx.x * blockDim.x + threadIdx.x;   // 0 .. 38911
    if (i < 16384) {
        g_w0h[i] = __float2half(W0[i]);
    } else if (i < 32768) {
        g_w1h[i - 16384] = __float2half(W1[i - 16384]);
    } else if (i < 32768 + 128 * 48) {
        int j = i - 32768;
        int r = j / 48, c = j % 48;
        g_w2h[j] = (c < 40) ? __float2half(W2[r * 40 + c]) : __half(0.f);
    }
}

// ---------------- smem-staged tensor-core GEMMs -------------------------------

// C[n,128](half) = A[n,128] @ W[128,128](half). BM=128, BK=64 (2 chunks).
// 256 threads = 8 warps in 2(m) x 4(n); warp tile 64x32 (4x2 fragments).
template <bool F32IN>
__global__ __launch_bounds__(256) void gemm128_smem(const void* __restrict__ Ain,
                                                    const __half* __restrict__ W,
                                                    __half2* __restrict__ C, int n) {
    __shared__ __half As[128][72];    // rows x K-chunk, padded
    __shared__ __half Ws[64][136];    // K-chunk x cols, padded
    __shared__ float  cs[8][16][20];  // per-warp epilogue staging

    const int tid = threadIdx.x;
    const int w = tid >> 5, lane = tid & 31;
    const int wm = w >> 2, wn = w & 3;
    const int row0 = blockIdx.x * 128;

    wmma::fragment<wmma::accumulator, 16, 16, 16, float> acc[4][2];
#pragma unroll
    for (int i = 0; i < 4; i++)
#pragma unroll
        for (int j = 0; j < 2; j++) wmma::fill_fragment(acc[i][j], 0.f);

#pragma unroll
    for (int kc = 0; kc < 2; kc++) {
        // stage A chunk: 128 rows x 64 K
        if (F32IN) {
            const float* A = (const float*)Ain;
#pragma unroll
            for (int it = 0; it < 8; it++) {
                int slot = tid + it * 256;         // 0..2047 float4 slots
                int r = slot >> 4, c4 = slot & 15; // 16 float4 per row
                float4 v = make_float4(0.f, 0.f, 0.f, 0.f);
                if (row0 + r < n)
                    v = *(const float4*)(A + (size_t)(row0 + r) * 128 + kc * 64 + c4 * 4);
                __half2* dst = (__half2*)&As[r][c4 * 4];
                dst[0] = __floats2half2_rn(v.x, v.y);
                dst[1] = __floats2half2_rn(v.z, v.w);
            }
        } else {
            const __half* A = (const __half*)Ain;
#pragma unroll
            for (int it = 0; it < 4; it++) {
                int slot = tid + it * 256;        // 0..1023 int4 slots
                int r = slot >> 3, c8 = slot & 7; // 8 int4 per row
                int4 v = make_int4(0, 0, 0, 0);
                if (row0 + r < n)
                    v = *(const int4*)(A + (size_t)(row0 + r) * 128 + kc * 64 + c8 * 8);
                *(int4*)&As[r][c8 * 8] = v;
            }
        }
        // stage W chunk: 64 K x 128 cols
#pragma unroll
        for (int it = 0; it < 4; it++) {
            int slot = tid + it * 256;             // 0..1023
            int r = slot >> 4, c8 = slot & 15;     // 16 int4 per row
            *(int4*)&Ws[r][c8 * 8] =
                *(const int4*)(W + (size_t)(kc * 64 + r) * 128 + c8 * 8);
        }
        __syncthreads();

#pragma unroll
        for (int k = 0; k < 4; k++) {
            wmma::fragment<wmma::matrix_b, 16, 16, 16, __half, wmma::row_major> b0, b1;
            wmma::load_matrix_sync(b0, &Ws[k * 16][wn * 32], 136);
            wmma::load_matrix_sync(b1, &Ws[k * 16][wn * 32 + 16], 136);
#pragma unroll
            for (int i = 0; i < 4; i++) {
                wmma::fragment<wmma::matrix_a, 16, 16, 16, __half, wmma::row_major> a;
                wmma::load_matrix_sync(a, &As[wm * 64 + i * 16][k * 16], 72);
                wmma::mma_sync(acc[i][0], a, b0, acc[i][0]);
                wmma::mma_sync(acc[i][1], a, b1, acc[i][1]);
            }
        }
        __syncthreads();
    }

    // epilogue: fragment -> smem(float) -> half2 global
    const int er = lane >> 3, ec = lane & 7;
#pragma unroll
    for (int i = 0; i < 4; i++)
#pragma unroll
        for (int j = 0; j < 2; j++) {
            wmma::store_matrix_sync(&cs[w][0][0], acc[i][j], 20, wmma::mem_row_major);
            __syncwarp();
#pragma unroll
            for (int t = 0; t < 4; t++) {
                int rr = er + t * 4;
                int gr = row0 + wm * 64 + i * 16 + rr;
                if (gr < n)
                    C[(size_t)gr * 64 + wn * 16 + j * 8 + ec] =
                        __floats2half2_rn(cs[w][rr][ec * 2], cs[w][rr][ec * 2 + 1]);
            }
            __syncwarp();
        }
}

// C[n,48](half) = A[n,128](half) @ W2h[128,48]. BM=128, 8 warps x 16 rows.
__global__ __launch_bounds__(256) void gemm40_smem(const __half* __restrict__ A,
                                                   __half2* __restrict__ C, int n) {
    __shared__ __half As[128][72];
    __shared__ __half Ws[64][56];
    __shared__ float  cs[8][16][20];

    const int tid = threadIdx.x;
    const int w = tid >> 5, lane = tid & 31;
    const int row0 = blockIdx.x * 128;

    wmma::fragment<wmma::accumulator, 16, 16, 16, float> acc[3];
#pragma unroll
    for (int j = 0; j < 3; j++) wmma::fill_fragment(acc[j], 0.f);

#pragma unroll
    for (int kc = 0; kc < 2; kc++) {
#pragma unroll
        for (int it = 0; it < 4; it++) {
            int slot = tid + it * 256;
            int r = slot >> 3, c8 = slot & 7;
            int4 v = make_int4(0, 0, 0, 0);
            if (row0 + r < n)
                v = *(const int4*)(A + (size_t)(row0 + r) * 128 + kc * 64 + c8 * 8);
            *(int4*)&As[r][c8 * 8] = v;
        }
        // W2 chunk: 64 rows x 48 cols = 384 int4 slots
        {
            int slot = tid;  // 256 threads, 2 passes cover 384
#pragma unroll
            for (int it = 0; it < 2; it++, slot += 256) {
                if (slot < 384) {
                    int r = slot / 6, c8 = slot % 6;
                    *(int4*)&Ws[r][c8 * 8] =
                        *(const int4*)(g_w2h + (size_t)(kc * 64 + r) * 48 + c8 * 8);
                }
            }
        }
        __syncthreads();

#pragma unroll
        for (int k = 0; k < 4; k++) {
            wmma::fragment<wmma::matrix_a, 16, 16, 16, __half, wmma::row_major> a;
            wmma::load_matrix_sync(a, &As[w * 16][k * 16], 72);
#pragma unroll
            for (int j = 0; j < 3; j++) {
                wmma::fragment<wmma::matrix_b, 16, 16, 16, __half, wmma::row_major> b;
                wmma::load_matrix_sync(b, &Ws[k * 16][j * 16], 56);
                wmma::mma_sync(acc[j], a, b, acc[j]);
            }
        }
        __syncthreads();
    }

    const int er = lane >> 3, ec = lane & 7;
#pragma unroll
    for (int j = 0; j < 3; j++) {
        wmma::store_matrix_sync(&cs[w][0][0], acc[j], 20, wmma::mem_row_major);
        __syncwarp();
#pragma unroll
        for (int t = 0; t < 4; t++) {
            int rr = er + t * 4;
            int gr = row0 + w * 16 + rr;
            if (gr < n)
                C[(size_t)gr * 24 + j * 8 + ec] =
                    __floats2half2_rn(cs[w][rr][ec * 2], cs[w][rr][ec * 2 + 1]);
        }
        __syncwarp();
    }
}

// ---------------- aggregation (one warp per destination node) ----------------

// 2 edges/iter: lanes 0-15 take even edges, 16-31 odd; each lane gathers one
// float4 (8 halfs) of the 128-wide row; merged via shfl_xor(16).
__global__ void aggregate128_kernel(const __half* __restrict__ tmp,
                                    const float* __restrict__ bias,
                                    __half* __restrict__ out, int n) {
    int w = (blockIdx.x * blockDim.x + threadIdx.x) >> 5;
    int lane = threadIdx.x & 31;
    if (w >= n) return;
    int beg = g_rowptr[w], end = g_rowptr[w + 1];
    const int g = lane >> 4, fl = lane & 15;

    float acc[8] = {0.f, 0.f, 0.f, 0.f, 0.f, 0.f, 0.f, 0.f};
    for (int e = beg + g; e < end; e += 2) {
        int s = g_col[e];
        float nw = g_norm[e];
        float4 v = *(const float4*)(tmp + (size_t)s * 128 + fl * 8);
        const __half2* h = (const __half2*)&v;
#pragma unroll
        for (int j = 0; j < 4; j++) {
            float2 f = __half22float2(h[j]);
            acc[2 * j]     = fmaf(nw, f.x, acc[2 * j]);
            acc[2 * j + 1] = fmaf(nw, f.y, acc[2 * j + 1]);
        }
    }
#pragma unroll
    for (int k = 0; k < 8; k++) acc[k] += __shfl_xor_sync(0xffffffffu, acc[k], 16);

    if (g == 0) {
        __half2 hv[4];
#pragma unroll
        for (int j = 0; j < 4; j++) {
            float a0 = fmaxf(acc[2 * j]     + bias[fl * 8 + 2 * j],     0.f);
            float a1 = fmaxf(acc[2 * j + 1] + bias[fl * 8 + 2 * j + 1], 0.f);
            hv[j] = __floats2half2_rn(a0, a1);
        }
        *(int4*)(out + (size_t)w * 128 + fl * 8) = *(const int4*)hv;
    }
}

// Reads padded [n,48]-half rows (24 half2), writes [n,40] fp32 (+bias, no relu).
__global__ void aggregate40_kernel(const __half2* __restrict__ tmp,
                                   const float* __restrict__ bias,
                                   float* __restrict__ out, int n) {
    int w = (blockIdx.x * blockDim.x + threadIdx.x) >> 5;
    int lane = threadIdx.x & 31;
    if (w >= n) return;
    int beg = g_rowptr[w], end = g_rowptr[w + 1];

    float2 acc = make_float2(0.f, 0.f);
    if (lane < 24) {
        int e = beg;
        for (; e + 1 < end; e += 2) {
            int s0 = g_col[e], s1 = g_col[e + 1];
            float n0 = g_norm[e], n1 = g_norm[e + 1];
            float2 f0 = __half22float2(tmp[(size_t)s0 * 24 + lane]);
            float2 f1 = __half22float2(tmp[(size_t)s1 * 24 + lane]);
            acc.x = fmaf(n0, f0.x, acc.x); acc.x = fmaf(n1, f1.x, acc.x);
            acc.y = fmaf(n0, f0.y, acc.y); acc.y = fmaf(n1, f1.y, acc.y);
        }
        if (e < end) {
            int s = g_col[e];
            float nw = g_norm[e];
            float2 f = __half22float2(tmp[(size_t)s * 24 + lane]);
            acc.x = fmaf(nw, f.x, acc.x);
            acc.y = fmaf(nw, f.y, acc.y);
        }
    }
    if (lane < 20) {
        out[(size_t)w * 40 + 2 * lane]     = acc.x + bias[2 * lane];
        out[(size_t)w * 40 + 2 * lane + 1] = acc.y + bias[2 * lane + 1];
    }
}

// ---------------- launch -----------------------------------------------------

extern "C" void kernel_launch(void* const* d_in, const int* in_sizes, int n_in,
                              void* d_out, int out_size) {
    const float* x  = (const float*)d_in[0];
    const int*   ei = (const int*)d_in[1];
    const float* W0 = (const float*)d_in[2];
    const float* b0 = (const float*)d_in[3];
    const float* W1 = (const float*)d_in[4];
    const float* b1 = (const float*)d_in[5];
    const float* W2 = (const float*)d_in[6];
    const float* b2 = (const float*)d_in[7];
    float* out = (float*)d_out;

    const int n = in_sizes[0] / 128;
    const int e = in_sizes[1] / 2;

    __half *bufA = nullptr, *bufB = nullptr, *w0h = nullptr, *w1h = nullptr;
    cudaGetSymbolAddress((void**)&bufA, g_bufA);
    cudaGetSymbolAddress((void**)&bufB, g_bufB);
    cudaGetSymbolAddress((void**)&w0h, g_w0h);
    cudaGetSymbolAddress((void**)&w1h, g_w1h);

    static cudaStream_t s_side = nullptr;
    static cudaEvent_t ev_fork = nullptr, ev_join = nullptr;
    if (!s_side) {
        cudaStreamCreateWithFlags(&s_side, cudaStreamNonBlocking);
        cudaEventCreateWithFlags(&ev_fork, cudaEventDisableTiming);
        cudaEventCreateWithFlags(&ev_join, cudaEventDisableTiming);
    }

    const int nb = (n + 1023) / 1024;
    const int gb = (n + 127) / 128;           // GEMM blocks (BM=128)
    const int ab = (n + 7) / 8;               // aggregate blocks (8 warps)

    // Fork: W conversion + layer-0 GEMM (reads x fp32 directly).
    cudaEventRecord(ev_fork, 0);
    cudaStreamWaitEvent(s_side, ev_fork, 0);
    convert_w_kernel<<<(32768 + 128 * 48 + 255) / 256, 256, 0, s_side>>>(W0, W1, W2);
    gemm128_smem<true><<<gb, 256, 0, s_side>>>(x, w0h, (__half2*)bufA, n);
    cudaEventRecord(ev_join, s_side);

    // Preprocessing chain on main stream (overlapped).
    zero_kernel<<<(n + 255) / 256, 256>>>(n);
    degree_kernel<<<(e + 255) / 256, 256>>>(ei, e);
    scan1_kernel<<<nb, 1024>>>(n);
    scan2_kernel<<<1, 128>>>(nb);
    scan3_kernel<<<(n + 255) / 256, 256>>>(n);
    fill_kernel<<<(e + n + 255) / 256, 256>>>(ei, e, n);

    cudaStreamWaitEvent(0, ev_join, 0);
    aggregate128_kernel<<<ab, 256>>>(bufA, b0, bufB, n);
    gemm128_smem<false><<<gb, 256>>>(bufB, w1h, (__half2*)bufA, n);
    aggregate128_kernel<<<ab, 256>>>(bufA, b1, bufB, n);
    gemm40_smem<<<gb, 256>>>(bufB, (__half2*)bufA, n);
    aggregate40_kernel<<<ab, 256>>>((const __half2*)bufA, b2, out, n);
}